// round 16
// baseline (speedup 1.0000x reference)
#include <cuda_runtime.h>
#include <cstdint>

#define NL 7
#define BATCH 524288
#define TPB 256
#define PPB (TPB * 2)           // poses per block = 512
#define GRIDN (BATCH / PPB)     // 1024
#define POSF (PPB * 3)          // floats per link in pos staging = 1536

typedef unsigned long long ull;

__device__ __forceinline__ ull f2pk(float lo, float hi) {
    ull r; asm("mov.b64 %0, {%1, %2};" : "=l"(r) : "f"(lo), "f"(hi)); return r;
}
__device__ __forceinline__ void f2upk(ull v, float& lo, float& hi) {
    asm("mov.b64 {%0, %1}, %2;" : "=f"(lo), "=f"(hi) : "l"(v));
}
__device__ __forceinline__ ull f2fma(ull a, ull b, ull c) {
    ull d; asm("fma.rn.f32x2 %0, %1, %2, %3;" : "=l"(d) : "l"(a), "l"(b), "l"(c)); return d;
}
__device__ __forceinline__ ull f2mul(ull a, ull b) {
    ull d; asm("mul.rn.f32x2 %0, %1, %2;" : "=l"(d) : "l"(a), "l"(b)); return d;
}
__device__ __forceinline__ ull f2add(ull a, ull b) {
    ull d; asm("add.rn.f32x2 %0, %1, %2;" : "=l"(d) : "l"(a), "l"(b)); return d;
}

__global__ __launch_bounds__(TPB, 4)
void fk_wt_kernel(const float* __restrict__ q,
                  const float* __restrict__ rot_fixed,
                  const float* __restrict__ trans_fixed,
                  float* __restrict__ out)
{
    __shared__ ull sF[NL * 4];                       // fixed quat, packed broadcast
    __shared__ ull sV[NL * 3];                       // fixed trans, packed broadcast
    __shared__ __align__(16) float sQ[PPB * NL];     // joint angles, 14KB
    __shared__ __align__(16) float sPos[NL * POSF];  // position staging, 42KB

    const int tid  = threadIdx.x;
    const int base = blockIdx.x * PPB;

    // ---- cooperative coalesced q load: 896 float4 (plain, like best R11) ----
    {
        const float4* gq4 = (const float4*)(q + (size_t)base * NL);
        float4* sq4 = (float4*)sQ;
        #pragma unroll
        for (int j = tid; j < (PPB * NL) / 4; j += TPB)
            sq4[j] = gq4[j];
    }

    // ---- fixed params -> packed broadcast (frozen values) ----
    if (tid < NL) {
        const float* R = rot_fixed + tid * 9;
        float r00 = R[0], r01 = R[1], r02 = R[2];
        float r10 = R[3], r11 = R[4], r12 = R[5];
        float r20 = R[6], r21 = R[7], r22 = R[8];
        const float eps = 1e-9f;
        float qw = 0.5f * sqrtf(fmaxf(1.f + r00 + r11 + r22, eps));
        float qx = 0.5f * sqrtf(fmaxf(1.f + r00 - r11 - r22, eps));
        float qy = 0.5f * sqrtf(fmaxf(1.f - r00 + r11 - r22, eps));
        float qz = 0.5f * sqrtf(fmaxf(1.f - r00 - r11 + r22, eps));
        qx = copysignf(qx, r21 - r12);
        qy = copysignf(qy, r02 - r20);
        qz = copysignf(qz, r10 - r01);
        sF[tid * 4 + 0] = f2pk(qx, qx);
        sF[tid * 4 + 1] = f2pk(qy, qy);
        sF[tid * 4 + 2] = f2pk(qz, qz);
        sF[tid * 4 + 3] = f2pk(qw, qw);
        const float* tf = trans_fixed + tid * 3;
        sV[tid * 3 + 0] = f2pk(tf[0], tf[0]);
        sV[tid * 3 + 1] = f2pk(tf[1], tf[1]);
        sV[tid * 3 + 2] = f2pk(tf[2], tf[2]);
    }
    __syncthreads();

    const ull M1  = f2pk(-1.f, -1.f);
    const ull TWO = f2pk(2.f, 2.f);

    // packed state: pose A in lo lane, pose B (b+256) in hi lane
    ull PX = 0, PY = 0, PZ = 0, PW = f2pk(1.f, 1.f);
    ull TX = 0, TY = 0, TZ = 0;

    const int b0 = base + tid;
    const int b1 = b0 + TPB;
    float4* qu_out = (float4*)(out + (size_t)NL * BATCH * 3);

    #pragma unroll
    for (int l = 0; l < NL; l++) {
        ull NPX = f2mul(PX, M1);
        ull NPY = f2mul(PY, M1);
        ull NPZ = f2mul(PZ, M1);

        // ---- t += rotate(p, tf) — frozen operand order ----
        {
            ull VX = sV[l * 3 + 0], VY = sV[l * 3 + 1], VZ = sV[l * 3 + 2];
            ull C1X = f2fma(PY, VZ, f2mul(NPZ, VY));
            ull C1Y = f2fma(PZ, VX, f2mul(NPX, VZ));
            ull C1Z = f2fma(PX, VY, f2mul(NPY, VX));
            ull C2X = f2fma(PW, C1X, f2fma(PY, C1Z, f2mul(NPZ, C1Y)));
            ull C2Y = f2fma(PW, C1Y, f2fma(PZ, C1X, f2mul(NPX, C1Z)));
            ull C2Z = f2fma(PW, C1Z, f2fma(PX, C1Y, f2mul(NPY, C1X)));
            TX = f2fma(TWO, C2X, f2add(TX, VX));
            TY = f2fma(TWO, C2Y, f2add(TY, VY));
            TZ = f2fma(TWO, C2Z, f2add(TZ, VZ));
        }

        // ---- m = p (x) qf[l] ----
        ull FX = sF[l * 4 + 0], FY = sF[l * 4 + 1], FZ = sF[l * 4 + 2], FW = sF[l * 4 + 3];
        ull MW = f2fma(PW, FW, f2fma(NPX, FX, f2fma(NPY, FY, f2mul(NPZ, FZ))));
        ull MX = f2fma(PW, FX, f2fma(PX,  FW, f2fma(PY,  FZ, f2mul(NPZ, FY))));
        ull MY = f2fma(PW, FY, f2fma(NPX, FZ, f2fma(PY,  FW, f2mul(PZ,  FX))));
        ull MZ = f2fma(PW, FZ, f2fma(PX,  FY, f2fma(NPY, FX, f2mul(PZ,  FW))));

        // ---- p = m (x) q_axis(half-angle) — frozen operand order ----
        {
            float a0 = sQ[tid * NL + l];
            float a1 = sQ[(tid + TPB) * NL + l];
            float s0, c0, s1, c1;
            __sincosf(0.5f * a0, &s0, &c0);
            __sincosf(0.5f * a1, &s1, &c1);
            ull S  = f2pk(s0, s1);
            ull C  = f2pk(c0, c1);
            ull NS = f2pk(-s0, -s1);

            if ((l & 1) == 0) {   // axis z
                PW = f2fma(MW, C, f2mul(MZ, NS));
                PX = f2fma(MX, C, f2mul(MY, S));
                PY = f2fma(MY, C, f2mul(MX, NS));
                PZ = f2fma(MW, S, f2mul(MZ, C));
            } else {              // axis y
                PW = f2fma(MW, C, f2mul(MY, NS));
                PX = f2fma(MX, C, f2mul(MZ, NS));
                PY = f2fma(MW, S, f2mul(MY, C));
                PZ = f2fma(MZ, C, f2mul(MX, S));
            }
        }

        // ---- stage positions (stride-3 STS, conflict-free) ----
        {
            float x0, x1, y0, y1, z0, z1;
            f2upk(TX, x0, x1); f2upk(TY, y0, y1); f2upk(TZ, z0, z1);
            float* p0 = &sPos[l * POSF + tid * 3];
            p0[0] = x0; p0[1] = y0; p0[2] = z0;
            float* p1 = &sPos[l * POSF + (tid + TPB) * 3];
            p1[0] = x1; p1[1] = y1; p1[2] = z1;
        }

        // ---- canonical quats (w>=0), WRITE-THROUGH float4 stores ----
        {
            float x0, x1, y0, y1, z0, z1, w0, w1;
            f2upk(PX, x0, x1); f2upk(PY, y0, y1);
            f2upk(PZ, z0, z1); f2upk(PW, w0, w1);
            float g0 = (w0 < 0.f) ? -1.f : 1.f;
            float g1 = (w1 < 0.f) ? -1.f : 1.f;
            __stwt(&qu_out[(size_t)l * BATCH + b0],
                   make_float4(g0 * x0, g0 * y0, g0 * z0, g0 * w0));
            __stwt(&qu_out[(size_t)l * BATCH + b1],
                   make_float4(g1 * x1, g1 * y1, g1 * z1, g1 * w1));
        }
    }

    __syncthreads();

    // ---- flush positions: WRITE-THROUGH coalesced float4 ----
    const float4* sp4 = (const float4*)sPos;
    #pragma unroll
    for (int l = 0; l < NL; l++) {
        float4* gp4 = (float4*)(out + ((size_t)l * BATCH + base) * 3);
        __stwt(&gp4[tid], sp4[l * (POSF / 4) + tid]);
        if (tid < POSF / 4 - TPB)   // 128 of 256 threads
            __stwt(&gp4[tid + TPB], sp4[l * (POSF / 4) + tid + TPB]);
    }
}

extern "C" void kernel_launch(void* const* d_in, const int* in_sizes, int n_in,
                              void* d_out, int out_size) {
    const float* q           = (const float*)d_in[0];
    const float* rot_fixed   = (const float*)d_in[1];
    const float* trans_fixed = (const float*)d_in[2];
    float* out = (float*)d_out;

    fk_wt_kernel<<<GRIDN, TPB>>>(q, rot_fixed, trans_fixed, out);
}

// round 17
// speedup vs baseline: 1.1780x; 1.1780x over previous
#include <cuda_runtime.h>
#include <cstdint>

#define NL 7
#define BATCH 524288
#define TPB 256
#define PPB (TPB * 2)           // poses per block = 512
#define GRIDN (BATCH / PPB)     // 1024
#define POSF (PPB * 3)          // floats per link in pos staging = 1536

typedef unsigned long long ull;

__device__ __forceinline__ ull f2pk(float lo, float hi) {
    ull r; asm("mov.b64 %0, {%1, %2};" : "=l"(r) : "f"(lo), "f"(hi)); return r;
}
__device__ __forceinline__ void f2upk(ull v, float& lo, float& hi) {
    asm("mov.b64 {%0, %1}, %2;" : "=f"(lo), "=f"(hi) : "l"(v));
}
__device__ __forceinline__ ull f2fma(ull a, ull b, ull c) {
    ull d; asm("fma.rn.f32x2 %0, %1, %2, %3;" : "=l"(d) : "l"(a), "l"(b), "l"(c)); return d;
}
__device__ __forceinline__ ull f2mul(ull a, ull b) {
    ull d; asm("mul.rn.f32x2 %0, %1, %2;" : "=l"(d) : "l"(a), "l"(b)); return d;
}
__device__ __forceinline__ ull f2add(ull a, ull b) {
    ull d; asm("add.rn.f32x2 %0, %1, %2;" : "=l"(d) : "l"(a), "l"(b)); return d;
}

__global__ __launch_bounds__(TPB, 4)
void fk_occ_kernel(const float* __restrict__ q,
                   const float* __restrict__ rot_fixed,
                   const float* __restrict__ trans_fixed,
                   float* __restrict__ out)
{
    __shared__ ull sF[NL * 4];                        // fixed quat, packed broadcast
    __shared__ ull sV[NL * 3];                        // fixed trans, packed broadcast
    __shared__ __align__(16) float sPos[4 * POSF];    // 4 link slots = 24.6KB

    const int tid  = threadIdx.x;
    const int base = blockIdx.x * PPB;

    // ---- fixed params -> packed broadcast (frozen values) ----
    if (tid < NL) {
        const float* R = rot_fixed + tid * 9;
        float r00 = R[0], r01 = R[1], r02 = R[2];
        float r10 = R[3], r11 = R[4], r12 = R[5];
        float r20 = R[6], r21 = R[7], r22 = R[8];
        const float eps = 1e-9f;
        float qw = 0.5f * sqrtf(fmaxf(1.f + r00 + r11 + r22, eps));
        float qx = 0.5f * sqrtf(fmaxf(1.f + r00 - r11 - r22, eps));
        float qy = 0.5f * sqrtf(fmaxf(1.f - r00 + r11 - r22, eps));
        float qz = 0.5f * sqrtf(fmaxf(1.f - r00 - r11 + r22, eps));
        qx = copysignf(qx, r21 - r12);
        qy = copysignf(qy, r02 - r20);
        qz = copysignf(qz, r10 - r01);
        sF[tid * 4 + 0] = f2pk(qx, qx);
        sF[tid * 4 + 1] = f2pk(qy, qy);
        sF[tid * 4 + 2] = f2pk(qz, qz);
        sF[tid * 4 + 3] = f2pk(qw, qw);
        const float* tf = trans_fixed + tid * 3;
        sV[tid * 3 + 0] = f2pk(tf[0], tf[0]);
        sV[tid * 3 + 1] = f2pk(tf[1], tf[1]);
        sV[tid * 3 + 2] = f2pk(tf[2], tf[2]);
    }

    // ---- per-thread joint angles: direct stride-7 LDG (path shown perf-neutral) ----
    const int b0 = base + tid;
    const int b1 = b0 + TPB;
    float qa[NL], qb[NL];
    #pragma unroll
    for (int i = 0; i < NL; i++) {
        qa[i] = __ldg(&q[(size_t)b0 * NL + i]);
        qb[i] = __ldg(&q[(size_t)b1 * NL + i]);
    }
    __syncthreads();

    const ull M1  = f2pk(-1.f, -1.f);
    const ull TWO = f2pk(2.f, 2.f);

    // packed state: pose A in lo lane, pose B (b+256) in hi lane
    ull PX = 0, PY = 0, PZ = 0, PW = f2pk(1.f, 1.f);
    ull TX = 0, TY = 0, TZ = 0;

    float4* qu_out = (float4*)(out + (size_t)NL * BATCH * 3);

    // one packed chain step + output staging; slot = sPos slot for this link
    #define FK_LINK(l, slot)                                                          \
    {                                                                                 \
        ull NPX = f2mul(PX, M1);                                                      \
        ull NPY = f2mul(PY, M1);                                                      \
        ull NPZ = f2mul(PZ, M1);                                                      \
        ull VX = sV[(l) * 3 + 0], VY = sV[(l) * 3 + 1], VZ = sV[(l) * 3 + 2];         \
        ull C1X = f2fma(PY, VZ, f2mul(NPZ, VY));                                      \
        ull C1Y = f2fma(PZ, VX, f2mul(NPX, VZ));                                      \
        ull C1Z = f2fma(PX, VY, f2mul(NPY, VX));                                      \
        ull C2X = f2fma(PW, C1X, f2fma(PY, C1Z, f2mul(NPZ, C1Y)));                    \
        ull C2Y = f2fma(PW, C1Y, f2fma(PZ, C1X, f2mul(NPX, C1Z)));                    \
        ull C2Z = f2fma(PW, C1Z, f2fma(PX, C1Y, f2mul(NPY, C1X)));                    \
        TX = f2fma(TWO, C2X, f2add(TX, VX));                                          \
        TY = f2fma(TWO, C2Y, f2add(TY, VY));                                          \
        TZ = f2fma(TWO, C2Z, f2add(TZ, VZ));                                          \
        ull FX = sF[(l)*4+0], FY = sF[(l)*4+1], FZ = sF[(l)*4+2], FW = sF[(l)*4+3];   \
        ull MW = f2fma(PW, FW, f2fma(NPX, FX, f2fma(NPY, FY, f2mul(NPZ, FZ))));       \
        ull MX = f2fma(PW, FX, f2fma(PX,  FW, f2fma(PY,  FZ, f2mul(NPZ, FY))));       \
        ull MY = f2fma(PW, FY, f2fma(NPX, FZ, f2fma(PY,  FW, f2mul(PZ,  FX))));       \
        ull MZ = f2fma(PW, FZ, f2fma(PX,  FY, f2fma(NPY, FX, f2mul(PZ,  FW))));       \
        float s0, c0, s1, c1;                                                         \
        __sincosf(0.5f * qa[l], &s0, &c0);                                            \
        __sincosf(0.5f * qb[l], &s1, &c1);                                            \
        ull S  = f2pk(s0, s1);                                                        \
        ull C  = f2pk(c0, c1);                                                        \
        ull NS = f2pk(-s0, -s1);                                                      \
        if (((l) & 1) == 0) {                                                         \
            PW = f2fma(MW, C, f2mul(MZ, NS));                                         \
            PX = f2fma(MX, C, f2mul(MY, S));                                          \
            PY = f2fma(MY, C, f2mul(MX, NS));                                         \
            PZ = f2fma(MW, S, f2mul(MZ, C));                                          \
        } else {                                                                      \
            PW = f2fma(MW, C, f2mul(MY, NS));                                         \
            PX = f2fma(MX, C, f2mul(MZ, NS));                                         \
            PY = f2fma(MW, S, f2mul(MY, C));                                          \
            PZ = f2fma(MZ, C, f2mul(MX, S));                                          \
        }                                                                             \
        {                                                                             \
            float x0, x1, y0, y1, z0, z1;                                             \
            f2upk(TX, x0, x1); f2upk(TY, y0, y1); f2upk(TZ, z0, z1);                  \
            float* p0 = &sPos[(slot) * POSF + tid * 3];                               \
            p0[0] = x0; p0[1] = y0; p0[2] = z0;                                       \
            float* p1 = &sPos[(slot) * POSF + (tid + TPB) * 3];                       \
            p1[0] = x1; p1[1] = y1; p1[2] = z1;                                       \
        }                                                                             \
        {                                                                             \
            float x0, x1, y0, y1, z0, z1, w0, w1;                                     \
            f2upk(PX, x0, x1); f2upk(PY, y0, y1);                                     \
            f2upk(PZ, z0, z1); f2upk(PW, w0, w1);                                     \
            float g0 = (w0 < 0.f) ? -1.f : 1.f;                                       \
            float g1 = (w1 < 0.f) ? -1.f : 1.f;                                       \
            __stcs(&qu_out[(size_t)(l) * BATCH + b0],                                 \
                   make_float4(g0 * x0, g0 * y0, g0 * z0, g0 * w0));                  \
            __stcs(&qu_out[(size_t)(l) * BATCH + b1],                                 \
                   make_float4(g1 * x1, g1 * y1, g1 * z1, g1 * w1));                  \
        }                                                                             \
    }

    // flush slot s -> link l: 384 float4, coalesced, no div/mod
    #define FLUSH_LINK(l, s)                                                          \
    {                                                                                 \
        const float4* sp4 = (const float4*)&sPos[(s) * POSF];                         \
        float4* gp4 = (float4*)(out + ((size_t)(l) * BATCH + base) * 3);              \
        __stcs(&gp4[tid], sp4[tid]);                                                  \
        if (tid < POSF / 4 - TPB)                                                     \
            __stcs(&gp4[tid + TPB], sp4[tid + TPB]);                                  \
    }

    FK_LINK(0, 0) FK_LINK(1, 1) FK_LINK(2, 2) FK_LINK(3, 3)
    __syncthreads();
    FLUSH_LINK(0, 0) FLUSH_LINK(1, 1) FLUSH_LINK(2, 2) FLUSH_LINK(3, 3)
    __syncthreads();
    FK_LINK(4, 0) FK_LINK(5, 1) FK_LINK(6, 2)
    __syncthreads();
    FLUSH_LINK(4, 0) FLUSH_LINK(5, 1) FLUSH_LINK(6, 2)

    #undef FK_LINK
    #undef FLUSH_LINK
}

extern "C" void kernel_launch(void* const* d_in, const int* in_sizes, int n_in,
                              void* d_out, int out_size) {
    const float* q           = (const float*)d_in[0];
    const float* rot_fixed   = (const float*)d_in[1];
    const float* trans_fixed = (const float*)d_in[2];
    float* out = (float*)d_out;

    fk_occ_kernel<<<GRIDN, TPB>>>(q, rot_fixed, trans_fixed, out);
}